// round 3
// baseline (speedup 1.0000x reference)
#include <cuda_runtime.h>
#include <math.h>

#define S_ 8192
#define D_ 64
#define N_ 2048
#define O_ 8
#define GATHER_BLOCKS 256                 // 256 x 256 thr = 65536 = S_*O_
#define LSE_BLOCKS (2 * N_ + O_ + N_ / 8) // 4360 arrival count

// ---- scratch (allocation-free rule: __device__ globals; BSS = 0) ----
__device__ float d_lse0[N_];
__device__ float d_lse1[N_];
__device__ float d_lse2[N_];
__device__ float d_lse_out[O_];
__device__ unsigned d_lse_done;   // arrivals from LSE blocks (reset each launch)
__device__ unsigned d_g_done;     // arrivals from gather blocks (reset each launch)

__device__ __forceinline__ unsigned ld_acquire_u32(const unsigned* p) {
    unsigned v;
    asm volatile("ld.acquire.gpu.u32 %0, [%1];" : "=r"(v) : "l"(p));
    return v;
}

// ---------------------------------------------------------------------------
// Single merged kernel.
//   blocks [0, GATHER_BLOCKS)  : path walk -> spin for LSE tables -> normalize
//   remaining blocks           : row-wise logsumexp + release-arrive on counter
// Gather blocks hold r0/r1/r2/logp in registers across the wait, so no scratch
// round-trip and no second launch.
// ---------------------------------------------------------------------------
__global__ void __launch_bounds__(256) occamnet_kernel(const float* __restrict__ x,
                                                       const float* __restrict__ w0,
                                                       const float* __restrict__ w1,
                                                       const float* __restrict__ w2,
                                                       const float* __restrict__ w_out,
                                                       const int* __restrict__ c0,
                                                       const int* __restrict__ c1,
                                                       const int* __restrict__ c2,
                                                       const int* __restrict__ keys_out,
                                                       float* __restrict__ out)
{
    __shared__ float smax[8];
    __shared__ float ssum[8];

    const int b = blockIdx.x;
    const int t = threadIdx.x;
    const int lane = t & 31;
    const int warp = t >> 5;

    if (b < GATHER_BLOCKS) {
        // ================= path-walk gather =================
        const int tid = b * 256 + t;
        const int s = tid >> 3;          // / O_
        const int o = tid & 7;           // % O_

        const int r2 = keys_out[tid];
        float logp = w_out[o * N_ + r2];

        const int r1 = c2[(size_t)s * N_ + r2];
        logp += w2[(size_t)r2 * N_ + r1];

        const int r0 = c1[(size_t)s * N_ + r1];
        logp += w1[(size_t)r1 * N_ + r0];

        const int cin = c0[(size_t)s * N_ + r0];
        logp += w0[r0 * D_ + cin];

        const float y = sinf(sinf(sinf(x[s * D_ + cin])));
        out[tid] = y;                                        // [0, S, O] slice

        // wait until every LSE block has published its row (thread 0 polls)
        if (t == 0) {
            while (ld_acquire_u32(&d_lse_done) < (unsigned)LSE_BLOCKS)
                __nanosleep(64);
        }
        __syncthreads();

        logp -= d_lse_out[o] + d_lse2[r2] + d_lse1[r1] + d_lse0[r0];
        out[S_ * O_ + tid] = expf(logp);                     // [1, S, O] slice

        // last gather block resets both counters for the next graph replay.
        // (All LSE arrivals strictly precede any gather passing the spin, so
        // zeroing here cannot race with an LSE increment of this launch.)
        if (t == 0) {
            unsigned old = atomicAdd(&d_g_done, 1u);
            if (old == GATHER_BLOCKS - 1) {
                atomicExch(&d_g_done, 0u);
                atomicExch(&d_lse_done, 0u);
            }
        }
        return;
    }

    const int b2 = b - GATHER_BLOCKS;
    if (b2 < 2 * N_ + O_) {
        // ================= wide rows: 2048 elements =================
        const float* row;
        float* dst;
        if (b2 < N_)          { row = w1    + (size_t)b2 * N_;           dst = &d_lse1[b2]; }
        else if (b2 < 2 * N_) { row = w2    + (size_t)(b2 - N_) * N_;    dst = &d_lse2[b2 - N_]; }
        else                  { row = w_out + (size_t)(b2 - 2*N_) * N_;  dst = &d_lse_out[b2 - 2*N_]; }

        const float4* row4 = (const float4*)row;
        float4 a = row4[t];
        float4 c = row4[t + 256];
        float v[8] = {a.x, a.y, a.z, a.w, c.x, c.y, c.z, c.w};

        float m = v[0];
        #pragma unroll
        for (int i = 1; i < 8; i++) m = fmaxf(m, v[i]);
        #pragma unroll
        for (int off = 16; off; off >>= 1) m = fmaxf(m, __shfl_xor_sync(0xffffffffu, m, off));
        if (lane == 0) smax[warp] = m;
        __syncthreads();
        float bm = smax[0];
        #pragma unroll
        for (int i = 1; i < 8; i++) bm = fmaxf(bm, smax[i]);

        float ss = 0.0f;
        #pragma unroll
        for (int i = 0; i < 8; i++) ss += expf(v[i] - bm);
        #pragma unroll
        for (int off = 16; off; off >>= 1) ss += __shfl_xor_sync(0xffffffffu, ss, off);
        if (lane == 0) ssum[warp] = ss;
        __syncthreads();
        if (t == 0) {
            float tot = 0.0f;
            #pragma unroll
            for (int i = 0; i < 8; i++) tot += ssum[i];
            *dst = bm + logf(tot);
            __threadfence();                 // release the row value
            atomicAdd(&d_lse_done, 1u);      // arrive
        }
    } else {
        // ================= w0: 64-wide rows, one warp per row =================
        const int r = (b2 - (2 * N_ + O_)) * 8 + warp;
        const float* row = w0 + (size_t)r * D_;
        float v0 = row[lane];
        float v1 = row[lane + 32];
        float m = fmaxf(v0, v1);
        #pragma unroll
        for (int off = 16; off; off >>= 1) m = fmaxf(m, __shfl_xor_sync(0xffffffffu, m, off));
        float ss = expf(v0 - m) + expf(v1 - m);
        #pragma unroll
        for (int off = 16; off; off >>= 1) ss += __shfl_xor_sync(0xffffffffu, ss, off);
        if (lane == 0) d_lse0[r] = m + logf(ss);
        __syncthreads();                     // all 8 rows of this block written
        if (t == 0) {
            __threadfence();                 // release
            atomicAdd(&d_lse_done, 1u);      // arrive
        }
    }
}

extern "C" void kernel_launch(void* const* d_in, const int* in_sizes, int n_in,
                              void* d_out, int out_size)
{
    const float* x     = (const float*)d_in[0];
    const float* w0    = (const float*)d_in[1];
    const float* w1    = (const float*)d_in[2];
    const float* w2    = (const float*)d_in[3];
    const float* w_out = (const float*)d_in[4];
    const int*   c0    = (const int*)d_in[5];
    const int*   c1    = (const int*)d_in[6];
    const int*   c2    = (const int*)d_in[7];
    const int*   keys  = (const int*)d_in[8];
    float*       out   = (float*)d_out;

    const int blocks = GATHER_BLOCKS + LSE_BLOCKS;
    occamnet_kernel<<<blocks, 256>>>(x, w0, w1, w2, w_out,
                                     c0, c1, c2, keys, out);
}

// round 4
// speedup vs baseline: 1.0152x; 1.0152x over previous
#include <cuda_runtime.h>
#include <math.h>

#define S_ 8192
#define D_ 64
#define N_ 2048
#define O_ 8
#define GATHER_BLOCKS 256                 // 256 x 256 thr = 65536 = S_*O_
#define LSE_BLOCKS (2 * N_ + O_ + N_ / 8) // 4360 arrival count

// ---- scratch (allocation-free rule: __device__ globals; BSS = 0) ----
__device__ float d_lse0[N_];
__device__ float d_lse1[N_];
__device__ float d_lse2[N_];
__device__ float d_lse_out[O_];
// Keep the arrival counter, the polled flag, and the gather counter on
// DIFFERENT cache lines: R3 regressed because high-rate polls and arrival
// atomics collided on one LTS address and serialized each other.
__device__ __align__(128) unsigned d_lse_done;           // LSE arrivals
__device__ __align__(128) volatile unsigned d_ready_flag; // set once by last LSE block
__device__ __align__(128) unsigned d_g_done;             // gather arrivals (for reset)

// ---------------------------------------------------------------------------
// Single merged kernel.
//   blocks [0, GATHER_BLOCKS)  : path walk -> cheap flag-wait -> normalize
//   remaining blocks           : row-wise logsumexp; last arrival sets flag
// Gather blocks go first so their memory-latency slack hides the LSE streaming
// (R2 evidence: combined phase ~9.2us, near HBM roofline).
// ---------------------------------------------------------------------------
__global__ void __launch_bounds__(256) occamnet_kernel(const float* __restrict__ x,
                                                       const float* __restrict__ w0,
                                                       const float* __restrict__ w1,
                                                       const float* __restrict__ w2,
                                                       const float* __restrict__ w_out,
                                                       const int* __restrict__ c0,
                                                       const int* __restrict__ c1,
                                                       const int* __restrict__ c2,
                                                       const int* __restrict__ keys_out,
                                                       float* __restrict__ out)
{
    __shared__ float smax[8];
    __shared__ float ssum[8];

    const int b = blockIdx.x;
    const int t = threadIdx.x;
    const int lane = t & 31;
    const int warp = t >> 5;

    if (b < GATHER_BLOCKS) {
        // ================= path-walk gather =================
        const int tid = b * 256 + t;
        const int s = tid >> 3;          // / O_
        const int o = tid & 7;           // % O_

        const int r2 = keys_out[tid];
        float logp = w_out[o * N_ + r2];

        const int r1 = c2[(size_t)s * N_ + r2];
        logp += w2[(size_t)r2 * N_ + r1];

        const int r0 = c1[(size_t)s * N_ + r1];
        logp += w1[(size_t)r1 * N_ + r0];

        const int cin = c0[(size_t)s * N_ + r0];
        logp += w0[r0 * D_ + cin];

        const float y = sinf(sinf(sinf(x[s * D_ + cin])));
        out[tid] = y;                                        // [0, S, O] slice

        // Low-rate wait for the single ready flag (one poller per block,
        // ~2K polls/s each -> negligible L2 traffic, <=~0.5us wake latency).
        if (t == 0) {
            while (d_ready_flag == 0u)
                __nanosleep(512);
            asm volatile("fence.acquire.gpu;" ::: "memory");
        }
        __syncthreads();

        logp -= __ldg(&d_lse_out[o]) + __ldg(&d_lse2[r2])
              + __ldg(&d_lse1[r1])   + __ldg(&d_lse0[r0]);
        out[S_ * O_ + tid] = expf(logp);                     // [1, S, O] slice

        // Last gather block resets counters/flag for the next graph replay.
        // (Every gather block observed flag==1 before arriving here, and
        // launches serialize on the stream, so the reset cannot race.)
        if (t == 0) {
            unsigned old = atomicAdd(&d_g_done, 1u);
            if (old == GATHER_BLOCKS - 1) {
                d_ready_flag = 0u;
                atomicExch(&d_lse_done, 0u);
                atomicExch(&d_g_done, 0u);
            }
        }
        return;
    }

    const int b2 = b - GATHER_BLOCKS;
    if (b2 < 2 * N_ + O_) {
        // ================= wide rows: 2048 elements =================
        const float* row;
        float* dst;
        if (b2 < N_)          { row = w1    + (size_t)b2 * N_;           dst = &d_lse1[b2]; }
        else if (b2 < 2 * N_) { row = w2    + (size_t)(b2 - N_) * N_;    dst = &d_lse2[b2 - N_]; }
        else                  { row = w_out + (size_t)(b2 - 2*N_) * N_;  dst = &d_lse_out[b2 - 2*N_]; }

        const float4* row4 = (const float4*)row;
        float4 a = row4[t];
        float4 c = row4[t + 256];
        float v[8] = {a.x, a.y, a.z, a.w, c.x, c.y, c.z, c.w};

        float m = v[0];
        #pragma unroll
        for (int i = 1; i < 8; i++) m = fmaxf(m, v[i]);
        #pragma unroll
        for (int off = 16; off; off >>= 1) m = fmaxf(m, __shfl_xor_sync(0xffffffffu, m, off));
        if (lane == 0) smax[warp] = m;
        __syncthreads();
        float bm = smax[0];
        #pragma unroll
        for (int i = 1; i < 8; i++) bm = fmaxf(bm, smax[i]);

        float ss = 0.0f;
        #pragma unroll
        for (int i = 0; i < 8; i++) ss += expf(v[i] - bm);
        #pragma unroll
        for (int off = 16; off; off >>= 1) ss += __shfl_xor_sync(0xffffffffu, ss, off);
        if (lane == 0) ssum[warp] = ss;
        __syncthreads();
        if (t == 0) {
            float tot = 0.0f;
            #pragma unroll
            for (int i = 0; i < 8; i++) tot += ssum[i];
            *dst = bm + logf(tot);
            __threadfence();                               // release the row value
            unsigned old = atomicAdd(&d_lse_done, 1u);     // arrive
            if (old == (unsigned)LSE_BLOCKS - 1) {
                __threadfence();
                d_ready_flag = 1u;                         // publish (volatile store)
            }
        }
    } else {
        // ================= w0: 64-wide rows, one warp per row =================
        const int r = (b2 - (2 * N_ + O_)) * 8 + warp;
        const float* row = w0 + (size_t)r * D_;
        float v0 = row[lane];
        float v1 = row[lane + 32];
        float m = fmaxf(v0, v1);
        #pragma unroll
        for (int off = 16; off; off >>= 1) m = fmaxf(m, __shfl_xor_sync(0xffffffffu, m, off));
        float ss = expf(v0 - m) + expf(v1 - m);
        #pragma unroll
        for (int off = 16; off; off >>= 1) ss += __shfl_xor_sync(0xffffffffu, ss, off);
        if (lane == 0) d_lse0[r] = m + logf(ss);
        __syncthreads();                                   // all 8 rows written
        if (t == 0) {
            __threadfence();                               // release
            unsigned old = atomicAdd(&d_lse_done, 1u);     // arrive
            if (old == (unsigned)LSE_BLOCKS - 1) {
                __threadfence();
                d_ready_flag = 1u;
            }
        }
    }
}

extern "C" void kernel_launch(void* const* d_in, const int* in_sizes, int n_in,
                              void* d_out, int out_size)
{
    const float* x     = (const float*)d_in[0];
    const float* w0    = (const float*)d_in[1];
    const float* w1    = (const float*)d_in[2];
    const float* w2    = (const float*)d_in[3];
    const float* w_out = (const float*)d_in[4];
    const int*   c0    = (const int*)d_in[5];
    const int*   c1    = (const int*)d_in[6];
    const int*   c2    = (const int*)d_in[7];
    const int*   keys  = (const int*)d_in[8];
    float*       out   = (float*)d_out;

    const int blocks = GATHER_BLOCKS + LSE_BLOCKS;
    occamnet_kernel<<<blocks, 256>>>(x, w0, w1, w2, w_out,
                                     c0, c1, c2, keys, out);
}